// round 2
// baseline (speedup 1.0000x reference)
#include <cuda_runtime.h>

#define KNEI 8
#define EHID 16

__device__ __forceinline__ float ex2f(float x) {
    float r; asm("ex2.approx.f32 %0, %1;" : "=f"(r) : "f"(x)); return r;
}

struct Net { float w[EHID]; float c[EHID]; float bias; int nnz; };
__device__ Net  g_nets[4];   // 0=rep, 1=att, 2=bor, 3=del
__device__ float g_scal[8];  // inv_p0, p1, ang^2, border[0], border[3]

// ---------------------------------------------------------------------------
// Fold each mono net  y = b2 + sum_i w2_i * exp(-(w1_i x + b1_i))
// into               y = bias + sum_{w1_i != 0} c_i * exp2(w'_i * x)
// ---------------------------------------------------------------------------
__global__ void sfm_preprocess(
    const float* __restrict__ rep_w1, const float* __restrict__ rep_b1,
    const float* __restrict__ rep_w2, const float* __restrict__ rep_b2,
    const float* __restrict__ att_w1, const float* __restrict__ att_b1,
    const float* __restrict__ att_w2, const float* __restrict__ att_b2,
    const float* __restrict__ bor_w1, const float* __restrict__ bor_b1,
    const float* __restrict__ bor_w2, const float* __restrict__ bor_b2,
    const float* __restrict__ del_w1, const float* __restrict__ del_b1,
    const float* __restrict__ del_w2, const float* __restrict__ del_b2,
    const float* __restrict__ p_dest, const float* __restrict__ angle,
    const float* __restrict__ border)
{
    int t = threadIdx.x;
    if (t < 4) {
        const float* w1 = (t==0)?rep_w1:(t==1)?att_w1:(t==2)?bor_w1:del_w1;
        const float* b1 = (t==0)?rep_b1:(t==1)?att_b1:(t==2)?bor_b1:del_b1;
        const float* w2 = (t==0)?rep_w2:(t==1)?att_w2:(t==2)?bor_w2:del_w2;
        const float* b2 = (t==0)?rep_b2:(t==1)?att_b2:(t==2)?bor_b2:del_b2;
        const float LOG2E = 1.4426950408889634f;
        float bias = b2[0];
        int m = 0;
        for (int i = 0; i < EHID; i++) {
            float ci = w2[i] * expf(-b1[i]);
            float wi = w1[i];
            if (wi != 0.0f) {
                g_nets[t].w[m] = -wi * LOG2E;
                g_nets[t].c[m] = ci;
                m++;
            } else {
                bias += ci;
            }
        }
        for (int i = m; i < EHID; i++) { g_nets[t].w[i] = 0.0f; g_nets[t].c[i] = 0.0f; }
        g_nets[t].bias = bias;
        g_nets[t].nnz  = m;
    } else if (t == 4) {
        g_scal[0] = 1.0f / p_dest[0];
        g_scal[1] = p_dest[1];
        float a = angle[0];
        g_scal[2] = a * a;
        g_scal[3] = border[0];
        g_scal[4] = border[3];
    }
}

template <int NB>
__device__ __forceinline__ void mono_batch(const float2* __restrict__ terms,
                                           int nn, float bias,
                                           const float* __restrict__ x,
                                           float* __restrict__ y)
{
#pragma unroll
    for (int k = 0; k < NB; k++) y[k] = bias;
    for (int t = 0; t < nn; t++) {
        float2 wc = terms[t];
#pragma unroll
        for (int k = 0; k < NB; k++)
            y[k] = fmaf(wc.y, ex2f(wc.x * x[k]), y[k]);
    }
}

__device__ __forceinline__ float mono1(const float2* __restrict__ terms,
                                       int nn, float bias, float x)
{
    float y = bias;
    for (int t = 0; t < nn; t++) {
        float2 wc = terms[t];
        y = fmaf(wc.y, ex2f(wc.x * x), y);
    }
    return y;
}

__global__ void __launch_bounds__(256)
sfm_main(const float* __restrict__ ego, const float* __restrict__ nei,
         const float* __restrict__ rec, float* __restrict__ out, int N)
{
    __shared__ float2 sT[4][EHID];
    __shared__ float  sB[4];
    __shared__ int    sN[4];
    __shared__ float  sS[8];

    int tid = threadIdx.x;
    if (tid < 64) {
        int q = tid >> 4, i = tid & 15;
        sT[q][i] = make_float2(g_nets[q].w[i], g_nets[q].c[i]);
    } else if (tid < 68) {
        sB[tid - 64] = g_nets[tid - 64].bias;
        sN[tid - 64] = g_nets[tid - 64].nnz;
    } else if (tid < 73) {
        sS[tid - 68] = g_scal[tid - 68];
    }
    __syncthreads();

    int n = blockIdx.x * 256 + tid;
    if (n >= N) return;

    // ================= front-batched DRAM loads (max MLP) =================
    // 8 neighbor ids: these LDGs also pull the 32B sectors that the later
    // per-neighbor float4 loads live in -> later loads are L1 hits.
    const float* nb = nei + (size_t)n * (KNEI * 16);
    float nid[8];
#pragma unroll
    for (int k = 0; k < 8; k++) nid[k] = __ldg(nb + (size_t)k * 16);

    const float4* e4 = reinterpret_cast<const float4*>(ego) + (size_t)n * 4;
    float4 e0 = e4[0], e1 = e4[1], e2 = e4[2], e3 = e4[3];

    const float4* r4 = reinterpret_cast<const float4*>(rec) + (size_t)n * 4;
    float4 rA = r4[0], rB = r4[1], rC = r4[2], rD = r4[3];

    // ================= scalar unpack =================
    float px = e0.y, py = e0.z;
    float vx = e0.w, vy = e1.x;
    float ids[8] = { e1.w, e2.x, e2.y, e2.z, e2.w, e3.x, e3.y, e3.z };

    float bid[8] = { rA.x, rA.z, rB.x, rB.z, rC.x, rC.z, rD.x, rD.z };
    float bct[8] = { rA.y, rA.w, rB.y, rB.w, rC.y, rC.w, rD.y, rD.w };

    // ================= buffer / count logic =================
    bool  ifin[8];
    float ct2[8];
#pragma unroll
    for (int k = 0; k < 8; k++) {
        bool f = false;
#pragma unroll
        for (int j = 0; j < 8; j++) f |= (bid[k] == nid[j]);
        ifin[k] = f;
        ct2[k]  = bct[k] + (f ? 1.0f : 0.0f);
    }

    float count[8];
#pragma unroll
    for (int i = 0; i < 8; i++) {
        float ci = 1.0f;
        int seen = 0;
#pragma unroll
        for (int k = 0; k < 8; k++) {
            bool take = ifin[k] && (seen == i);
            ci = take ? ct2[k] : ci;
            seen += ifin[k] ? 1 : 0;
        }
        count[i] = ci;
    }

    // neighbor validity: nid[k] in ego ids and nid != 0
    bool idxk[8];
#pragma unroll
    for (int k = 0; k < 8; k++) {
        bool m = false;
#pragma unroll
        for (int j = 0; j < 8; j++) m |= (nid[k] == ids[j]);
        idxk[k] = m && (nid[k] != 0.0f);
    }

    float v2   = vx * vx + vy * vy;
    float ang2 = sS[2];

    // ================= del net: warp-uniform fast path =================
    // If every lane has all-equal counts (true when recording_time is all
    // zeros), evaluate the del net once per lane instead of 8 times.
    bool same = true;
#pragma unroll
    for (int i = 1; i < 8; i++) same &= (count[i] == count[0]);
    unsigned amask = __activemask();
    bool del_fast = __all_sync(amask, same);
    float del_u = 0.0f;
    if (del_fast) del_u = mono1(sT[3], sN[3], sB[3], count[0]);

    // ================= per-neighbor work, two halves of 4 =================
    float fnx = 0.0f, fny = 0.0f;
#pragma unroll
    for (int h = 0; h < 2; h++) {
        float dx[4], dy[4], rn4[4], bv4[4];
#pragma unroll
        for (int j = 0; j < 4; j++) {
            int k = h * 4 + j;
            // L1 hits (sector already fetched by nid load)
            float4 a  = *reinterpret_cast<const float4*>(nb + (size_t)k * 16);
            float vny = __ldg(nb + (size_t)k * 16 + 4);

            float rx = a.y - px, ry = a.z - py;
            float s  = rx * rx + ry * ry;
            float ir = rsqrtf(s);
            rn4[j] = s * ir;
            dx[j]  = rx * ir;
            dy[j]  = ry * ir;

            float vdx = a.w * 0.02f, vdy = vny * 0.02f;
            float tx = rx + vdx, ty = ry + vdy;
            float bb = rn4[j] + tx * tx + ty * ty - (vdx * vdx + vdy * vdy);
            bb = idxk[k] ? bb : 1.0f;
            bv4[j] = __fsqrt_rn(fmaxf(bb, 1e-12f)) * 0.5f;
        }

        float att4[4], rep4[4], del4[4];
        mono_batch<4>(sT[1], sN[1], sB[1], rn4, att4);
        mono_batch<4>(sT[0], sN[0], sB[0], bv4, rep4);
        if (del_fast) {
#pragma unroll
            for (int j = 0; j < 4; j++) del4[j] = del_u;
        } else {
            mono_batch<4>(sT[3], sN[3], sB[3], &count[h * 4], del4);
        }

#pragma unroll
        for (int j = 0; j < 4; j++) {
            int k = h * 4 + j;
            bool ix = idxk[k];
            float da  = del4[j] * att4[j];
            float fax = ix ? da * dx[j] : 0.0f;
            float fay = ix ? da * dy[j] : 0.0f;
            float frx = ix ? rep4[j] * dx[j] : 0.0f;
            float fry = ix ? rep4[j] * dy[j] : 0.0f;

            float num = vx * fax + vy * fay;
            float nn  = fax * fax + fay * fay;
            bool keep = num * num > ang2 * fmaxf(v2 * nn, 1e-16f);
            fnx += keep ? fax : 0.0f;
            fny += keep ? fay : 0.0f;

            num  = vx * frx + vy * fry;
            nn   = frx * frx + fry * fry;
            keep = num * num > ang2 * fmaxf(v2 * nn, 1e-16f);
            fnx += keep ? frx : 0.0f;
            fny += keep ? fry : 0.0f;
        }
    }

    // ================= destination force =================
    float speed = __fsqrt_rn(v2);
    float ip0 = sS[0], p1 = sS[1];
    float fdx = (p1 * speed - vx) * ip0;
    float fdy = (-vy) * ip0;
    {
        float num = vx * fdx + vy * fdy;
        float nn  = fdx * fdx + fdy * fdy;
        bool keep = num * num > ang2 * fmaxf(v2 * nn, 1e-16f);
        fdx = keep ? fdx : 0.0f;
        fdy = keep ? fdy : 0.0f;
    }

    // ================= border force (y only) =================
    float bxc = e0.z;
    float rb0 = bxc - sS[3];
    float rb1 = bxc - sS[4];
    float rbn[2] = { fabsf(rb0), fabsf(rb1) };
    float bmag[2];
    mono_batch<2>(sT[2], sN[2], sB[2], rbn, bmag);
    float fby = 0.0f;
    {
        float fv = bmag[0] * copysignf(1.0f, rb0);
        float num = vy * fv, nn = fv * fv;
        if (num * num > ang2 * fmaxf(v2 * nn, 1e-16f)) fby += fv;
        fv = bmag[1] * copysignf(1.0f, rb1);
        num = vy * fv; nn = fv * fv;
        if (num * num > ang2 * fmaxf(v2 * nn, 1e-16f)) fby += fv;
    }

    // ================= output: (N, 3, 2) =================
    float2* o = reinterpret_cast<float2*>(out) + (size_t)n * 3;
    o[0] = make_float2(fdx, fdy);
    o[1] = make_float2(fnx, fny);
    o[2] = make_float2(0.0f, fby);
}

extern "C" void kernel_launch(void* const* d_in, const int* in_sizes, int n_in,
                              void* d_out, int out_size)
{
    const float* ego    = (const float*)d_in[0];
    const float* nei    = (const float*)d_in[1];
    const float* border = (const float*)d_in[2];
    const float* rec    = (const float*)d_in[3];
    const float* p_dest = (const float*)d_in[4];
    const float* angle  = (const float*)d_in[5];

    sfm_preprocess<<<1, 32>>>(
        (const float*)d_in[6],  (const float*)d_in[7],  (const float*)d_in[8],  (const float*)d_in[9],
        (const float*)d_in[10], (const float*)d_in[11], (const float*)d_in[12], (const float*)d_in[13],
        (const float*)d_in[14], (const float*)d_in[15], (const float*)d_in[16], (const float*)d_in[17],
        (const float*)d_in[18], (const float*)d_in[19], (const float*)d_in[20], (const float*)d_in[21],
        p_dest, angle, border);

    int N = in_sizes[0] / 16;
    int blocks = (N + 255) / 256;
    sfm_main<<<blocks, 256>>>(ego, nei, rec, (float*)d_out, N);
}

// round 3
// speedup vs baseline: 1.2981x; 1.2981x over previous
#include <cuda_runtime.h>

#define KNEI 8
#define EHID 16

__device__ __forceinline__ float ex2f(float x) {
    float r; asm("ex2.approx.f32 %0, %1;" : "=f"(r) : "f"(x)); return r;
}

struct Net { float w[EHID]; float c[EHID]; float bias; int nnz; };
__device__ Net  g_nets[4];   // 0=rep, 1=att, 2=bor, 3=del
__device__ float g_scal[8];  // inv_p0, p1, ang^2, border[0], border[3]

// ---------------------------------------------------------------------------
// Fold each mono net  y = b2 + sum_i w2_i * exp(-(w1_i x + b1_i))
// into               y = bias + sum_{w1_i != 0} c_i * exp2(w'_i * x)
// ---------------------------------------------------------------------------
__global__ void sfm_preprocess(
    const float* __restrict__ rep_w1, const float* __restrict__ rep_b1,
    const float* __restrict__ rep_w2, const float* __restrict__ rep_b2,
    const float* __restrict__ att_w1, const float* __restrict__ att_b1,
    const float* __restrict__ att_w2, const float* __restrict__ att_b2,
    const float* __restrict__ bor_w1, const float* __restrict__ bor_b1,
    const float* __restrict__ bor_w2, const float* __restrict__ bor_b2,
    const float* __restrict__ del_w1, const float* __restrict__ del_b1,
    const float* __restrict__ del_w2, const float* __restrict__ del_b2,
    const float* __restrict__ p_dest, const float* __restrict__ angle,
    const float* __restrict__ border)
{
    int t = threadIdx.x;
    if (t < 4) {
        const float* w1 = (t==0)?rep_w1:(t==1)?att_w1:(t==2)?bor_w1:del_w1;
        const float* b1 = (t==0)?rep_b1:(t==1)?att_b1:(t==2)?bor_b1:del_b1;
        const float* w2 = (t==0)?rep_w2:(t==1)?att_w2:(t==2)?bor_w2:del_w2;
        const float* b2 = (t==0)?rep_b2:(t==1)?att_b2:(t==2)?bor_b2:del_b2;
        const float LOG2E = 1.4426950408889634f;
        float bias = b2[0];
        int m = 0;
        for (int i = 0; i < EHID; i++) {
            float ci = w2[i] * expf(-b1[i]);
            float wi = w1[i];
            if (wi != 0.0f) {
                g_nets[t].w[m] = -wi * LOG2E;
                g_nets[t].c[m] = ci;
                m++;
            } else {
                bias += ci;
            }
        }
        for (int i = m; i < EHID; i++) { g_nets[t].w[i] = 0.0f; g_nets[t].c[i] = 0.0f; }
        g_nets[t].bias = bias;
        g_nets[t].nnz  = m;
    } else if (t == 4) {
        g_scal[0] = 1.0f / p_dest[0];
        g_scal[1] = p_dest[1];
        float a = angle[0];
        g_scal[2] = a * a;
        g_scal[3] = border[0];
        g_scal[4] = border[3];
    }
}

template <int NB>
__device__ __forceinline__ void mono_batch(const float2* __restrict__ terms,
                                           int nn, float bias,
                                           const float* __restrict__ x,
                                           float* __restrict__ y)
{
#pragma unroll
    for (int k = 0; k < NB; k++) y[k] = bias;
    for (int t = 0; t < nn; t++) {
        float2 wc = terms[t];
#pragma unroll
        for (int k = 0; k < NB; k++)
            y[k] = fmaf(wc.y, ex2f(wc.x * x[k]), y[k]);
    }
}

__device__ __forceinline__ float mono1(const float2* __restrict__ terms,
                                       int nn, float bias, float x)
{
    float y = bias;
    for (int t = 0; t < nn; t++) {
        float2 wc = terms[t];
        y = fmaf(wc.y, ex2f(wc.x * x), y);
    }
    return y;
}

__global__ void __launch_bounds__(256)
sfm_main(const float* __restrict__ ego, const float* __restrict__ nei,
         const float* __restrict__ rec, float* __restrict__ out, int N)
{
    __shared__ float2 sT[4][EHID];
    __shared__ float  sB[4];
    __shared__ int    sN[4];
    __shared__ float  sS[8];

    int tid = threadIdx.x;
    if (tid < 64) {
        int q = tid >> 4, i = tid & 15;
        sT[q][i] = make_float2(g_nets[q].w[i], g_nets[q].c[i]);
    } else if (tid < 68) {
        sB[tid - 64] = g_nets[tid - 64].bias;
        sN[tid - 64] = g_nets[tid - 64].nnz;
    } else if (tid < 73) {
        sS[tid - 68] = g_scal[tid - 68];
    }
    __syncthreads();

    int n = blockIdx.x * 256 + tid;
    if (n >= N) return;

    // ============ ALL global loads front-batched, loaded exactly once ======
    const float* nb = nei + (size_t)n * (KNEI * 16);
    float4 af[8];
    float  vn[8];
#pragma unroll
    for (int k = 0; k < 8; k++)
        af[k] = *reinterpret_cast<const float4*>(nb + (size_t)k * 16); // id,px,py,vnx
#pragma unroll
    for (int k = 0; k < 8; k++)
        vn[k] = __ldg(nb + (size_t)k * 16 + 4);                         // vny

    const float4* e4 = reinterpret_cast<const float4*>(ego) + (size_t)n * 4;
    float4 e0 = e4[0], e1 = e4[1], e2 = e4[2], e3 = e4[3];

    const float4* r4 = reinterpret_cast<const float4*>(rec) + (size_t)n * 4;
    float4 rA = r4[0], rB = r4[1], rC = r4[2], rD = r4[3];

    // ============ unpack ego =============
    float px = e0.y, py = e0.z;
    float vx = e0.w, vy = e1.x;
    float ids[8] = { e1.w, e2.x, e2.y, e2.z, e2.w, e3.x, e3.y, e3.z };

    // ============ neighbor validity + geometry (consumes af/vn) ============
    bool  idxk[8];
    float rnv[8], bv[8], dx[8], dy[8];
#pragma unroll
    for (int k = 0; k < 8; k++) {
        float id = af[k].x;
        bool m = false;
#pragma unroll
        for (int j = 0; j < 8; j++) m |= (id == ids[j]);
        bool ix = m && (id != 0.0f);
        idxk[k] = ix;

        float rx = af[k].y - px, ry = af[k].z - py;
        float s  = rx * rx + ry * ry;
        float ir = rsqrtf(s);
        float rn = s * ir;
        rnv[k] = rn;
        dx[k]  = rx * ir;
        dy[k]  = ry * ir;

        float vdx = af[k].w * 0.02f, vdy = vn[k] * 0.02f;
        float tx = rx + vdx, ty = ry + vdy;
        float bb = rn + tx * tx + ty * ty - (vdx * vdx + vdy * vdy);
        bb = ix ? bb : 1.0f;
        bv[k] = __fsqrt_rn(fmaxf(bb, 1e-12f)) * 0.5f;
    }

    // ============ att / rep nets (independent of rec) ============
    float att8[8], rep8[8];
    mono_batch<8>(sT[1], sN[1], sB[1], rnv, att8);
    mono_batch<8>(sT[0], sN[0], sB[0], bv,  rep8);

    // ============ buffer / count logic (rec latency hidden by monos above) =
    float bid[8] = { rA.x, rA.z, rB.x, rB.z, rC.x, rC.z, rD.x, rD.z };
    float bct[8] = { rA.y, rA.w, rB.y, rB.w, rC.y, rC.w, rD.y, rD.w };

    bool  ifin[8];
    float ct2[8];
#pragma unroll
    for (int k = 0; k < 8; k++) {
        bool f = false;
#pragma unroll
        for (int j = 0; j < 8; j++) f |= (bid[k] == af[j].x);
        ifin[k] = f;
        ct2[k]  = bct[k] + (f ? 1.0f : 0.0f);
    }

    float count[8];
#pragma unroll
    for (int i = 0; i < 8; i++) {
        float ci = 1.0f;
        int seen = 0;
#pragma unroll
        for (int k = 0; k < 8; k++) {
            bool take = ifin[k] && (seen == i);
            ci = take ? ct2[k] : ci;
            seen += ifin[k] ? 1 : 0;
        }
        count[i] = ci;
    }

    // ============ del net (warp-uniform fast path) ============
    bool same = true;
#pragma unroll
    for (int i = 1; i < 8; i++) same &= (count[i] == count[0]);
    unsigned amask = __activemask();
    float del8[8];
    if (__all_sync(amask, same)) {
        float du = mono1(sT[3], sN[3], sB[3], count[0]);
#pragma unroll
        for (int k = 0; k < 8; k++) del8[k] = du;
    } else {
        mono_batch<8>(sT[3], sN[3], sB[3], count, del8);
    }

    float v2   = vx * vx + vy * vy;
    float ang2 = sS[2];

    // ============ neighbor forces, angle-clamped (squared form) ============
    float fnx = 0.0f, fny = 0.0f;
#pragma unroll
    for (int k = 0; k < 8; k++) {
        bool ix = idxk[k];
        float da  = del8[k] * att8[k];
        float fax = ix ? da * dx[k] : 0.0f;
        float fay = ix ? da * dy[k] : 0.0f;
        float frx = ix ? rep8[k] * dx[k] : 0.0f;
        float fry = ix ? rep8[k] * dy[k] : 0.0f;

        float num = vx * fax + vy * fay;
        float nn  = fax * fax + fay * fay;
        bool keep = num * num > ang2 * fmaxf(v2 * nn, 1e-16f);
        fnx += keep ? fax : 0.0f;
        fny += keep ? fay : 0.0f;

        num  = vx * frx + vy * fry;
        nn   = frx * frx + fry * fry;
        keep = num * num > ang2 * fmaxf(v2 * nn, 1e-16f);
        fnx += keep ? frx : 0.0f;
        fny += keep ? fry : 0.0f;
    }

    // ============ destination force ============
    float speed = __fsqrt_rn(v2);
    float ip0 = sS[0], p1 = sS[1];
    float fdx = (p1 * speed - vx) * ip0;
    float fdy = (-vy) * ip0;
    {
        float num = vx * fdx + vy * fdy;
        float nn  = fdx * fdx + fdy * fdy;
        bool keep = num * num > ang2 * fmaxf(v2 * nn, 1e-16f);
        fdx = keep ? fdx : 0.0f;
        fdy = keep ? fdy : 0.0f;
    }

    // ============ border force (y only) ============
    float bxc = e0.z;
    float rb0 = bxc - sS[3];
    float rb1 = bxc - sS[4];
    float rbn[2] = { fabsf(rb0), fabsf(rb1) };
    float bmag[2];
    mono_batch<2>(sT[2], sN[2], sB[2], rbn, bmag);
    float fby = 0.0f;
    {
        float fv = bmag[0] * copysignf(1.0f, rb0);
        float num = vy * fv, nn = fv * fv;
        if (num * num > ang2 * fmaxf(v2 * nn, 1e-16f)) fby += fv;
        fv = bmag[1] * copysignf(1.0f, rb1);
        num = vy * fv; nn = fv * fv;
        if (num * num > ang2 * fmaxf(v2 * nn, 1e-16f)) fby += fv;
    }

    // ============ output: (N, 3, 2) ============
    float2* o = reinterpret_cast<float2*>(out) + (size_t)n * 3;
    o[0] = make_float2(fdx, fdy);
    o[1] = make_float2(fnx, fny);
    o[2] = make_float2(0.0f, fby);
}

extern "C" void kernel_launch(void* const* d_in, const int* in_sizes, int n_in,
                              void* d_out, int out_size)
{
    const float* ego    = (const float*)d_in[0];
    const float* nei    = (const float*)d_in[1];
    const float* border = (const float*)d_in[2];
    const float* rec    = (const float*)d_in[3];
    const float* p_dest = (const float*)d_in[4];
    const float* angle  = (const float*)d_in[5];

    sfm_preprocess<<<1, 32>>>(
        (const float*)d_in[6],  (const float*)d_in[7],  (const float*)d_in[8],  (const float*)d_in[9],
        (const float*)d_in[10], (const float*)d_in[11], (const float*)d_in[12], (const float*)d_in[13],
        (const float*)d_in[14], (const float*)d_in[15], (const float*)d_in[16], (const float*)d_in[17],
        (const float*)d_in[18], (const float*)d_in[19], (const float*)d_in[20], (const float*)d_in[21],
        p_dest, angle, border);

    int N = in_sizes[0] / 16;
    int blocks = (N + 255) / 256;
    sfm_main<<<blocks, 256>>>(ego, nei, rec, (float*)d_out, N);
}